// round 5
// baseline (speedup 1.0000x reference)
#include <cuda_runtime.h>
#include <math.h>

#define Bdim 4
#define Sdim 2048
#define Ddim 1024
#define Hdim 16
#define HDdim 64
#define Fdim 4096
#define Mdim (Bdim * Sdim)   // 8192
#define EPS 1e-5f

// ---------------------------------------------------------------------------
// Scratch: 11 * M * D floats = 369 MB static device memory (allowed workaround
// for the no-alloc rule).
//   [0]  xn1      (M*D)
//   [1]  q        (M*D)  layout [B,H,S,HD]
//   [2]  k        (M*D)
//   [3]  v        (M*D)
//   [4]  attnout  (M*D)  layout [B,S,D]
//   [5]  x1       (M*D)
//   [6]  xn2      (M*D)
//   [7..10] h     (M*F = 4*M*D)
// ---------------------------------------------------------------------------
#define MD ((size_t)Mdim * Ddim)
__device__ float g_scratch[11 * MD];

// ===========================================================================
// LayerNorm: one block (256 threads) per row of 1024 floats.
// ===========================================================================
__global__ __launch_bounds__(256) void ln_kernel(const float* __restrict__ X,
                                                 const float* __restrict__ G,
                                                 const float* __restrict__ Bt,
                                                 float* __restrict__ Y) {
    int row = blockIdx.x;
    int t = threadIdx.x;
    const float4* xr = (const float4*)(X + (size_t)row * Ddim);
    float4 v = xr[t];
    float s  = v.x + v.y + v.z + v.w;
    float ss = v.x * v.x + v.y * v.y + v.z * v.z + v.w * v.w;

    // warp reduce
    #pragma unroll
    for (int off = 16; off > 0; off >>= 1) {
        s  += __shfl_xor_sync(0xffffffffu, s,  off);
        ss += __shfl_xor_sync(0xffffffffu, ss, off);
    }
    __shared__ float red_s[8], red_q[8];
    int wid = t >> 5, lane = t & 31;
    if (lane == 0) { red_s[wid] = s; red_q[wid] = ss; }
    __syncthreads();
    float S_ = 0.f, Q_ = 0.f;
    #pragma unroll
    for (int i = 0; i < 8; i++) { S_ += red_s[i]; Q_ += red_q[i]; }

    float mu   = S_ * (1.0f / Ddim);
    float var  = Q_ * (1.0f / Ddim) - mu * mu;
    float rstd = rsqrtf(var + EPS);

    float4 g4 = ((const float4*)G)[t];
    float4 b4 = ((const float4*)Bt)[t];
    float4 y;
    y.x = (v.x - mu) * rstd * g4.x + b4.x;
    y.y = (v.y - mu) * rstd * g4.y + b4.y;
    y.z = (v.z - mu) * rstd * g4.z + b4.z;
    y.w = (v.w - mu) * rstd * g4.w + b4.w;
    ((float4*)(Y + (size_t)row * Ddim))[t] = y;
}

// ===========================================================================
// SGEMM: C[M,N] = A[M,K] @ W[K,N] + bias, with epilogue modes.
// BM=BN=128, BK=8, 256 threads, 8x8 microtile, double-buffered smem.
// ===========================================================================
#define MODE_PLAIN 0
#define MODE_RES   1
#define MODE_GELU  2
#define MODE_QKV   3

template <int MODE>
__global__ __launch_bounds__(256) void sgemm_kernel(
    const float* __restrict__ A, const float* __restrict__ W,
    const float* __restrict__ bias, const float* __restrict__ Res,
    float* __restrict__ C, int Mn, int Nn, int Kn) {
    __shared__ float As[2][8][128];
    __shared__ float Bs[2][8][128];

    int t  = threadIdx.x;
    int bm = blockIdx.y * 128;
    int bn = blockIdx.x * 128;

    int ar = t >> 1;            // 0..127  A row within tile
    int ak = (t & 1) * 4;       // 0 or 4  A k offset
    int bkr = t >> 5;           // 0..7    B k row
    int bc  = (t & 31) * 4;     // 0..124  B col offset
    int tx = t & 15, ty = t >> 4;

    const float* Ap = A + (size_t)(bm + ar) * Kn + ak;
    const float* Bp = W + (size_t)bkr * Nn + bn + bc;

    // preload tile 0
    float4 pa = *(const float4*)Ap;
    float4 pb = *(const float4*)Bp;
    As[0][ak + 0][ar] = pa.x;
    As[0][ak + 1][ar] = pa.y;
    As[0][ak + 2][ar] = pa.z;
    As[0][ak + 3][ar] = pa.w;
    *(float4*)&Bs[0][bkr][bc] = pb;
    __syncthreads();

    float c[8][8];
    #pragma unroll
    for (int i = 0; i < 8; i++)
        #pragma unroll
        for (int j = 0; j < 8; j++) c[i][j] = 0.f;

    int ntiles = Kn >> 3;
    int sbuf = 0;
    for (int tile = 0; tile < ntiles; tile++) {
        if (tile + 1 < ntiles) {
            pa = *(const float4*)(Ap + (tile + 1) * 8);
            pb = *(const float4*)(Bp + (size_t)(tile + 1) * 8 * Nn);
        }
        #pragma unroll
        for (int kk = 0; kk < 8; kk++) {
            float4 a0 = *(float4*)&As[sbuf][kk][ty * 8];
            float4 a1 = *(float4*)&As[sbuf][kk][ty * 8 + 4];
            float4 b0 = *(float4*)&Bs[sbuf][kk][tx * 8];
            float4 b1 = *(float4*)&Bs[sbuf][kk][tx * 8 + 4];
            float av[8] = {a0.x, a0.y, a0.z, a0.w, a1.x, a1.y, a1.z, a1.w};
            float bv[8] = {b0.x, b0.y, b0.z, b0.w, b1.x, b1.y, b1.z, b1.w};
            #pragma unroll
            for (int i = 0; i < 8; i++)
                #pragma unroll
                for (int j = 0; j < 8; j++) c[i][j] += av[i] * bv[j];
        }
        if (tile + 1 < ntiles) {
            As[sbuf ^ 1][ak + 0][ar] = pa.x;
            As[sbuf ^ 1][ak + 1][ar] = pa.y;
            As[sbuf ^ 1][ak + 2][ar] = pa.z;
            As[sbuf ^ 1][ak + 3][ar] = pa.w;
            *(float4*)&Bs[sbuf ^ 1][bkr][bc] = pb;
        }
        __syncthreads();
        sbuf ^= 1;
    }

    // epilogue
    #pragma unroll
    for (int i = 0; i < 8; i++) {
        int m = bm + ty * 8 + i;
        #pragma unroll
        for (int j4 = 0; j4 < 8; j4 += 4) {
            int n = bn + tx * 8 + j4;
            float4 vv;
            float4 bb = *(const float4*)(bias + n);
            vv.x = c[i][j4 + 0] + bb.x;
            vv.y = c[i][j4 + 1] + bb.y;
            vv.z = c[i][j4 + 2] + bb.z;
            vv.w = c[i][j4 + 3] + bb.w;
            if (MODE == MODE_RES) {
                float4 rr = *(const float4*)(Res + (size_t)m * Nn + n);
                vv.x += rr.x; vv.y += rr.y; vv.z += rr.z; vv.w += rr.w;
            }
            if (MODE == MODE_GELU) {
                vv.x = 0.5f * vv.x * (1.f + erff(vv.x * 0.70710678118654752f));
                vv.y = 0.5f * vv.y * (1.f + erff(vv.y * 0.70710678118654752f));
                vv.z = 0.5f * vv.z * (1.f + erff(vv.z * 0.70710678118654752f));
                vv.w = 0.5f * vv.w * (1.f + erff(vv.w * 0.70710678118654752f));
            }
            if (MODE == MODE_QKV) {
                // [B,S,D] row m, col n  ->  [B,H,S,HD]
                int b_ = m >> 11;          // m / S
                int s_ = m & 2047;         // m % S
                int h_ = n >> 6;           // n / HD
                int hd = n & 63;           // n % HD
                size_t o = ((((size_t)b_ * Hdim + h_) * Sdim + s_) * HDdim) + hd;
                *(float4*)(C + o) = vv;
            } else {
                *(float4*)(C + (size_t)m * Nn + n) = vv;
            }
        }
    }
}

// ===========================================================================
// Flash-style attention.  Grid: (S/64, B*H), 256 threads.
// Q,K,V in [B,H,S,HD]; output written in [B,S,D].
// smem: q_sm[d][q], k_sm[d][j], v_sm[j][d], p_sm[j][q]; rows padded to 68.
// ===========================================================================
#define PAD 68
#define ATTN_SMEM (4 * 64 * PAD * 4)

__global__ __launch_bounds__(256) void attention_kernel(
    const float* __restrict__ Q, const float* __restrict__ K,
    const float* __restrict__ V, float* __restrict__ O) {
    extern __shared__ float sm[];
    float* q_sm = sm;                    // [64][PAD]  (d-major)
    float* k_sm = sm + 64 * PAD;         // [64][PAD]  (d-major)
    float* v_sm = sm + 2 * 64 * PAD;     // [64][PAD]  (j-major)
    float* p_sm = sm + 3 * 64 * PAD;     // [64][PAD]  (k-major)

    int t  = threadIdx.x;
    int bh = blockIdx.y;                 // b*H + h
    int q0 = blockIdx.x * 64;
    int b_ = bh / Hdim, h_ = bh % Hdim;

    const float* Qb = Q + ((size_t)bh * Sdim + q0) * HDdim;
    const float* Kb = K + (size_t)bh * Sdim * HDdim;
    const float* Vb = V + (size_t)bh * Sdim * HDdim;

    int tq = t >> 4;   // 0..15 : query group (4 queries)
    int tk = t & 15;   // 0..15 : key/dim group (4 cols)

    // load Q tile transposed, pre-scaled by 1/sqrt(HD)
    #pragma unroll
    for (int r = 0; r < 4; r++) {
        int f = t + r * 256;             // float4 index, 0..1023
        int row = f >> 4;                // query 0..63
        int dc = (f & 15) << 2;          // dim 0..60
        float4 qv = *(const float4*)(Qb + row * HDdim + dc);
        q_sm[(dc + 0) * PAD + row] = qv.x * 0.125f;
        q_sm[(dc + 1) * PAD + row] = qv.y * 0.125f;
        q_sm[(dc + 2) * PAD + row] = qv.z * 0.125f;
        q_sm[(dc + 3) * PAD + row] = qv.w * 0.125f;
    }

    float o_acc[4][4];
    #pragma unroll
    for (int i = 0; i < 4; i++)
        #pragma unroll
        for (int j = 0; j < 4; j++) o_acc[i][j] = 0.f;
    float m_run[4] = {-1e30f, -1e30f, -1e30f, -1e30f};
    float l_run[4] = {0.f, 0.f, 0.f, 0.f};

    for (int kt = 0; kt < Sdim / 64; kt++) {
        __syncthreads();   // protect k_sm/v_sm/p_sm reuse from previous iter
        const float* Kt = Kb + (size_t)kt * 64 * HDdim;
        const float* Vt = Vb + (size_t)kt * 64 * HDdim;
        #pragma unroll
        for (int r = 0; r < 4; r++) {
            int f = t + r * 256;
            int row = f >> 4;
            int dc = (f & 15) << 2;
            float4 kv = *(const float4*)(Kt + row * HDdim + dc);
            k_sm[(dc + 0) * PAD + row] = kv.x;
            k_sm[(dc + 1) * PAD + row] = kv.y;
            k_sm[(dc + 2) * PAD + row] = kv.z;
            k_sm[(dc + 3) * PAD + row] = kv.w;
            float4 vv = *(const float4*)(Vt + row * HDdim + dc);
            *(float4*)&v_sm[row * PAD + dc] = vv;
        }
        __syncthreads();

        // scores: s[4q][4k]
        float s4[4][4];
        #pragma unroll
        for (int i = 0; i < 4; i++)
            #pragma unroll
            for (int j = 0; j < 4; j++) s4[i][j] = 0.f;
        #pragma unroll 8
        for (int d = 0; d < 64; d++) {
            float4 aq = *(float4*)&q_sm[d * PAD + tq * 4];
            float4 bk = *(float4*)&k_sm[d * PAD + tk * 4];
            float av[4] = {aq.x, aq.y, aq.z, aq.w};
            float bv[4] = {bk.x, bk.y, bk.z, bk.w};
            #pragma unroll
            for (int i = 0; i < 4; i++)
                #pragma unroll
                for (int j = 0; j < 4; j++) s4[i][j] += av[i] * bv[j];
        }

        // online softmax per query row (row group = 16 lanes sharing tq)
        #pragma unroll
        for (int qi = 0; qi < 4; qi++) {
            float tmax = fmaxf(fmaxf(s4[qi][0], s4[qi][1]),
                               fmaxf(s4[qi][2], s4[qi][3]));
            #pragma unroll
            for (int off = 8; off > 0; off >>= 1)
                tmax = fmaxf(tmax, __shfl_xor_sync(0xffffffffu, tmax, off));
            float m_new = fmaxf(m_run[qi], tmax);
            float alpha = __expf(m_run[qi] - m_new);
            m_run[qi] = m_new;
            float psum = 0.f;
            #pragma unroll
            for (int j = 0; j < 4; j++) {
                s4[qi][j] = __expf(s4[qi][j] - m_new);
                psum += s4[qi][j];
            }
            #pragma unroll
            for (int off = 8; off > 0; off >>= 1)
                psum += __shfl_xor_sync(0xffffffffu, psum, off);
            l_run[qi] = l_run[qi] * alpha + psum;
            #pragma unroll
            for (int j = 0; j < 4; j++) o_acc[qi][j] *= alpha;
            // write p transposed: p_sm[key][query]
            #pragma unroll
            for (int j = 0; j < 4; j++)
                p_sm[(tk * 4 + j) * PAD + tq * 4 + qi] = s4[qi][j];
        }
        __syncthreads();

        // o += p @ V : tk now serves as dim group
        #pragma unroll 8
        for (int kk = 0; kk < 64; kk++) {
            float4 pp = *(float4*)&p_sm[kk * PAD + tq * 4];
            float4 vv = *(float4*)&v_sm[kk * PAD + tk * 4];
            float pv[4] = {pp.x, pp.y, pp.z, pp.w};
            float vvv[4] = {vv.x, vv.y, vv.z, vv.w};
            #pragma unroll
            for (int i = 0; i < 4; i++)
                #pragma unroll
                for (int j = 0; j < 4; j++) o_acc[i][j] += pv[i] * vvv[j];
        }
    }

    // write output in [B,S,D]
    #pragma unroll
    for (int qi = 0; qi < 4; qi++) {
        float inv = 1.0f / l_run[qi];
        int qrow = q0 + tq * 4 + qi;
        float4 r;
        r.x = o_acc[qi][0] * inv;
        r.y = o_acc[qi][1] * inv;
        r.z = o_acc[qi][2] * inv;
        r.w = o_acc[qi][3] * inv;
        size_t off = ((size_t)b_ * Sdim + qrow) * Ddim + h_ * HDdim + tk * 4;
        *(float4*)(O + off) = r;
    }
}

// ===========================================================================
// Launch
// ===========================================================================
extern "C" void kernel_launch(void* const* d_in, const int* in_sizes, int n_in,
                              void* d_out, int out_size) {
    const float* x   = (const float*)d_in[0];
    const float* Wq  = (const float*)d_in[1];
    const float* bq  = (const float*)d_in[2];
    const float* Wk  = (const float*)d_in[3];
    const float* bk  = (const float*)d_in[4];
    const float* Wv  = (const float*)d_in[5];
    const float* bv  = (const float*)d_in[6];
    const float* Wo  = (const float*)d_in[7];
    const float* bo  = (const float*)d_in[8];
    const float* W1  = (const float*)d_in[9];
    const float* b1  = (const float*)d_in[10];
    const float* W2  = (const float*)d_in[11];
    const float* b2  = (const float*)d_in[12];
    const float* g1  = (const float*)d_in[13];
    const float* be1 = (const float*)d_in[14];
    const float* g2  = (const float*)d_in[15];
    const float* be2 = (const float*)d_in[16];
    float* out = (float*)d_out;

    float* base = nullptr;
    cudaGetSymbolAddress((void**)&base, g_scratch);
    float* xn  = base;
    float* q   = base + 1 * MD;
    float* k   = base + 2 * MD;
    float* v   = base + 3 * MD;
    float* att = base + 4 * MD;
    float* x1  = base + 5 * MD;
    float* xn2 = base + 6 * MD;
    float* h   = base + 7 * MD;

    cudaFuncSetAttribute(attention_kernel,
                         cudaFuncAttributeMaxDynamicSharedMemorySize,
                         ATTN_SMEM);

    dim3 blk(256);
    dim3 gD(Ddim / 128, Mdim / 128);   // N=1024 GEMMs
    dim3 gF(Fdim / 128, Mdim / 128);   // N=4096 GEMM

    ln_kernel<<<Mdim, blk>>>(x, g1, be1, xn);
    sgemm_kernel<MODE_QKV><<<gD, blk>>>(xn, Wq, bq, nullptr, q, Mdim, Ddim, Ddim);
    sgemm_kernel<MODE_QKV><<<gD, blk>>>(xn, Wk, bk, nullptr, k, Mdim, Ddim, Ddim);
    sgemm_kernel<MODE_QKV><<<gD, blk>>>(xn, Wv, bv, nullptr, v, Mdim, Ddim, Ddim);
    attention_kernel<<<dim3(Sdim / 64, Bdim * Hdim), blk, ATTN_SMEM>>>(q, k, v, att);
    sgemm_kernel<MODE_RES><<<gD, blk>>>(att, Wo, bo, x, x1, Mdim, Ddim, Ddim);
    ln_kernel<<<Mdim, blk>>>(x1, g2, be2, xn2);
    sgemm_kernel<MODE_GELU><<<gF, blk>>>(xn2, W1, b1, nullptr, h, Mdim, Fdim, Ddim);
    sgemm_kernel<MODE_RES><<<gD, blk>>>(h, W2, b2, x1, out, Mdim, Ddim, Fdim);
}

// round 7
// speedup vs baseline: 1.6858x; 1.6858x over previous
#include <cuda_runtime.h>
#include <cuda_bf16.h>
#include <math.h>
#include <stdint.h>

#define Bdim 4
#define Sdim 2048
#define Ddim 1024
#define Hdim 16
#define HDdim 64
#define Fdim 4096
#define Mdim (Bdim * Sdim)   // 8192
#define EPS 1e-5f

#define MDsz ((size_t)Mdim * Ddim)
#define MFsz ((size_t)Mdim * Fdim)
#define DDsz ((size_t)Ddim * Ddim)
#define DFsz ((size_t)Ddim * Fdim)

// ---------------- scratch (static device arrays; allocation-free) ----------
__device__ float g_qkv[3 * MDsz];          // q,k,v fp32 [B,H,S,HD]
__device__ float g_x1[MDsz];               // residual after attention
__device__ float g_b3[3 * Ddim];           // concat bias q|k|v
__device__ __nv_bfloat16 g_xn_hi[MDsz],  g_xn_lo[MDsz];
__device__ __nv_bfloat16 g_att_hi[MDsz], g_att_lo[MDsz];
__device__ __nv_bfloat16 g_xn2_hi[MDsz], g_xn2_lo[MDsz];
__device__ __nv_bfloat16 g_h_hi[MFsz],   g_h_lo[MFsz];
__device__ __nv_bfloat16 g_wqkv_hi[3*DDsz], g_wqkv_lo[3*DDsz];  // [3072,1024] K-major
__device__ __nv_bfloat16 g_wo_hi[DDsz],  g_wo_lo[DDsz];         // [1024,1024]
__device__ __nv_bfloat16 g_w1_hi[DFsz],  g_w1_lo[DFsz];         // [4096,1024]
__device__ __nv_bfloat16 g_w2_hi[DFsz],  g_w2_lo[DFsz];         // [1024,4096]

// ---------------- PTX helpers (baseline sm_80+ only) ------------------------
__device__ __forceinline__ uint32_t smem_u32(const void* p) {
    uint32_t a;
    asm("{ .reg .u64 t; cvta.to.shared.u64 t, %1; cvt.u32.u64 %0, t; }"
        : "=r"(a) : "l"(p));
    return a;
}
#define CPA16(d, s) asm volatile("cp.async.cg.shared.global [%0], [%1], 16;" :: "r"(d), "l"(s))
#define CPCOMMIT()  asm volatile("cp.async.commit_group;" ::: "memory")
#define CPWAIT1()   asm volatile("cp.async.wait_group 1;" ::: "memory")
#define CPWAIT0()   asm volatile("cp.async.wait_group 0;" ::: "memory")

#define LDSM4(r0, r1, r2, r3, a) \
    asm volatile("ldmatrix.sync.aligned.m8n8.x4.shared.b16 {%0,%1,%2,%3}, [%4];" \
                 : "=r"(r0), "=r"(r1), "=r"(r2), "=r"(r3) : "r"(a))
#define LDSM2(r0, r1, a) \
    asm volatile("ldmatrix.sync.aligned.m8n8.x2.shared.b16 {%0,%1}, [%2];" \
                 : "=r"(r0), "=r"(r1) : "r"(a))
#define MMA16816(c, a, b) \
    asm volatile("mma.sync.aligned.m16n8k16.row.col.f32.bf16.bf16.f32 " \
                 "{%0,%1,%2,%3}, {%4,%5,%6,%7}, {%8,%9}, {%0,%1,%2,%3};" \
                 : "+f"((c)[0]), "+f"((c)[1]), "+f"((c)[2]), "+f"((c)[3]) \
                 : "r"((a)[0]), "r"((a)[1]), "r"((a)[2]), "r"((a)[3]), \
                   "r"((b)[0]), "r"((b)[1]))

__device__ __forceinline__ void split_bf16(float v, __nv_bfloat16& hi, __nv_bfloat16& lo) {
    hi = __float2bfloat16(v);
    lo = __float2bfloat16(v - __bfloat162float(hi));
}

// ===========================================================================
// LayerNorm -> bf16 hi/lo split. one block (256 thr) per row of 1024.
// ===========================================================================
__global__ __launch_bounds__(256) void ln_split(const float* __restrict__ X,
                                                const float* __restrict__ G,
                                                const float* __restrict__ Bt,
                                                __nv_bfloat16* __restrict__ Yhi,
                                                __nv_bfloat16* __restrict__ Ylo) {
    int row = blockIdx.x, t = threadIdx.x;
    float4 v = ((const float4*)(X + (size_t)row * Ddim))[t];
    float s  = v.x + v.y + v.z + v.w;
    float ss = v.x*v.x + v.y*v.y + v.z*v.z + v.w*v.w;
    #pragma unroll
    for (int off = 16; off > 0; off >>= 1) {
        s  += __shfl_xor_sync(0xffffffffu, s,  off);
        ss += __shfl_xor_sync(0xffffffffu, ss, off);
    }
    __shared__ float rs[8], rq[8];
    int wid = t >> 5, lane = t & 31;
    if (lane == 0) { rs[wid] = s; rq[wid] = ss; }
    __syncthreads();
    float S_ = 0.f, Q_ = 0.f;
    #pragma unroll
    for (int i = 0; i < 8; i++) { S_ += rs[i]; Q_ += rq[i]; }
    float mu = S_ * (1.0f / Ddim);
    float rstd = rsqrtf(Q_ * (1.0f / Ddim) - mu * mu + EPS);
    float4 g4 = ((const float4*)G)[t];
    float4 b4 = ((const float4*)Bt)[t];
    float y[4] = {(v.x-mu)*rstd*g4.x + b4.x, (v.y-mu)*rstd*g4.y + b4.y,
                  (v.z-mu)*rstd*g4.z + b4.z, (v.w-mu)*rstd*g4.w + b4.w};
    size_t off = (size_t)row * Ddim + t * 4;
    #pragma unroll
    for (int i = 0; i < 4; i++) {
        __nv_bfloat16 hi, lo; split_bf16(y[i], hi, lo);
        Yhi[off + i] = hi; Ylo[off + i] = lo;
    }
}

// ===========================================================================
// Weight transpose + split: W[K,N] fp32 -> Whi/Wlo [N,K] bf16 (K-major).
// ===========================================================================
__global__ __launch_bounds__(256) void wsplit(const float* __restrict__ W,
                                              __nv_bfloat16* __restrict__ Whi,
                                              __nv_bfloat16* __restrict__ Wlo,
                                              int K, int N) {
    __shared__ float tile[32][33];
    int tx = threadIdx.x & 31, ty = threadIdx.x >> 5;   // 32 x 8
    int bn = blockIdx.x * 32, bk = blockIdx.y * 32;
    #pragma unroll
    for (int i = 0; i < 4; i++)
        tile[ty + i*8][tx] = W[(size_t)(bk + ty + i*8) * N + bn + tx];
    __syncthreads();
    #pragma unroll
    for (int i = 0; i < 4; i++) {
        int n = bn + ty + i*8, k = bk + tx;
        __nv_bfloat16 hi, lo; split_bf16(tile[tx][ty + i*8], hi, lo);
        Whi[(size_t)n * K + k] = hi;
        Wlo[(size_t)n * K + k] = lo;
    }
}

__global__ void bias3(const float* a, const float* b, const float* c, float* o) {
    int i = blockIdx.x * 256 + threadIdx.x;
    if (i < 3072)
        o[i] = i < 1024 ? a[i] : (i < 2048 ? b[i - 1024] : c[i - 2048]);
}

// ===========================================================================
// split-bf16 GEMM on mma.sync (HMMA).  C[M,N] = A @ B^T, B K-major [N,K].
// BM=BN=128, BK=32, 256 thr = 8 warps (2 m x 4 n), warp tile 64x32.
// SMEM: per stage 4 arrays (Ahi,Alo,Bhi,Blo), each 128 rows x 80B (32 bf16 +
// pad).  Row stride 80B => ldmatrix conflict-free.
// MODE 0: QKV scatter (+bias)    MODE 1: +bias +Res -> fp32
// MODE 2: gelu(+bias) -> bf16 hi/lo
// ===========================================================================
#define STG_ARR 10240                 // 128 * 80
#define STG_BYTES (4 * STG_ARR)       // 40960
#define GEMM_SMEM (2 * STG_BYTES)     // 81920

template <int MODE>
__global__ __launch_bounds__(256) void gemm_tc(
    const __nv_bfloat16* __restrict__ Ahi, const __nv_bfloat16* __restrict__ Alo,
    const __nv_bfloat16* __restrict__ Bhi, const __nv_bfloat16* __restrict__ Blo,
    const float* __restrict__ bias, const float* __restrict__ Res,
    float* __restrict__ outF, __nv_bfloat16* __restrict__ outHi,
    __nv_bfloat16* __restrict__ outLo, int Nn, int Kn) {
    extern __shared__ char smem[];
    uint32_t sb = smem_u32(smem);
    int t = threadIdx.x;
    int lane = t & 31, wid = t >> 5;
    int warp_m = wid >> 2;             // 0..1 -> m offset 0/64
    int warp_n = wid & 3;              // 0..3 -> n offset 0/32/64/96
    int bm = blockIdx.y * 128, bn = blockIdx.x * 128;
    int ktiles = Kn >> 5;

    // prefetch one k-tile (BK=32) into stage s
    auto prefetch = [&](int kt, int s) {
        uint32_t stg = sb + s * STG_BYTES;
        #pragma unroll
        for (int it = 0; it < 8; it++) {
            int cid = t + it * 256;          // 0..2047
            int arr = cid >> 9;              // 0 Ahi,1 Alo,2 Bhi,3 Blo
            int rem = cid & 511;
            int row = rem >> 2, ch = rem & 3;
            uint32_t dst = stg + arr * STG_ARR + row * 80 + ch * 16;
            const __nv_bfloat16* src;
            if (arr == 0)      src = Ahi + (size_t)(bm + row) * Kn;
            else if (arr == 1) src = Alo + (size_t)(bm + row) * Kn;
            else if (arr == 2) src = Bhi + (size_t)(bn + row) * Kn;
            else               src = Blo + (size_t)(bn + row) * Kn;
            src += kt * 32 + ch * 8;
            CPA16(dst, src);
        }
        CPCOMMIT();
    };

    float acc[4][4][4];                 // [mt][nt][frag]
    #pragma unroll
    for (int i = 0; i < 4; i++)
        #pragma unroll
        for (int j = 0; j < 4; j++)
            #pragma unroll
            for (int r = 0; r < 4; r++) acc[i][j][r] = 0.f;

    prefetch(0, 0);
    if (ktiles > 1) prefetch(1, 1);

    // ldmatrix lane address components
    int aLr = lane & 15, aLc = lane >> 4;        // A: row sel, k-chunk sel
    int bLr = lane & 7,  bLc = (lane >> 3) & 1;  // B: row sel, k-chunk sel

    for (int kt = 0; kt < ktiles; kt++) {
        int s = kt & 1;
        if (kt + 1 < ktiles) { CPWAIT1(); } else { CPWAIT0(); }
        __syncthreads();
        uint32_t stg = sb + s * STG_BYTES;
        uint32_t aHiB = stg,             aLoB = stg + STG_ARR;
        uint32_t bHiB = stg + 2*STG_ARR, bLoB = stg + 3*STG_ARR;

        #pragma unroll
        for (int ks = 0; ks < 2; ks++) {
            int k0 = ks * 16;
            uint32_t ahi[4][4], alo[4][4], bhi[4][2], blo[4][2];
            #pragma unroll
            for (int mt = 0; mt < 4; mt++) {
                uint32_t off = (uint32_t)(warp_m * 64 + mt * 16 + aLr) * 80
                             + (uint32_t)(k0 + aLc * 8) * 2;
                LDSM4(ahi[mt][0], ahi[mt][1], ahi[mt][2], ahi[mt][3], aHiB + off);
                LDSM4(alo[mt][0], alo[mt][1], alo[mt][2], alo[mt][3], aLoB + off);
            }
            #pragma unroll
            for (int nt = 0; nt < 4; nt++) {
                uint32_t off = (uint32_t)(warp_n * 32 + nt * 8 + bLr) * 80
                             + (uint32_t)(k0 + bLc * 8) * 2;
                LDSM2(bhi[nt][0], bhi[nt][1], bHiB + off);
                LDSM2(blo[nt][0], blo[nt][1], bLoB + off);
            }
            #pragma unroll
            for (int mt = 0; mt < 4; mt++)
                #pragma unroll
                for (int nt = 0; nt < 4; nt++) {
                    MMA16816(acc[mt][nt], ahi[mt], bhi[nt]);
                    MMA16816(acc[mt][nt], alo[mt], bhi[nt]);
                    MMA16816(acc[mt][nt], ahi[mt], blo[nt]);
                }
        }
        __syncthreads();
        if (kt + 2 < ktiles) prefetch(kt + 2, s);
    }

    // ---------------- epilogue ----------------
    int g = lane >> 2, t4 = lane & 3;
    int m_base = bm + warp_m * 64;
    int n_base = bn + warp_n * 32;

    float bcol[4][2];
    #pragma unroll
    for (int nt = 0; nt < 4; nt++) {
        int col = n_base + nt * 8 + t4 * 2;
        bcol[nt][0] = bias[col];
        bcol[nt][1] = bias[col + 1];
    }

    #pragma unroll
    for (int mt = 0; mt < 4; mt++) {
        #pragma unroll
        for (int half = 0; half < 2; half++) {
            int m = m_base + mt * 16 + g + half * 8;
            int b_ = m >> 11, s_ = m & 2047;
            #pragma unroll
            for (int nt = 0; nt < 4; nt++) {
                int col = n_base + nt * 8 + t4 * 2;
                float v0 = acc[mt][nt][half * 2 + 0] + bcol[nt][0];
                float v1 = acc[mt][nt][half * 2 + 1] + bcol[nt][1];
                if (MODE == 0) {
                    int mat = col >> 10;
                    int nn = col & 1023;
                    int h_ = nn >> 6, hd = nn & 63;
                    float* dst = outF + (size_t)mat * MDsz
                               + ((((size_t)b_ * Hdim + h_) * Sdim + s_) << 6) + hd;
                    float2 w; w.x = v0; w.y = v1;
                    *(float2*)dst = w;
                } else if (MODE == 1) {
                    size_t off = (size_t)m * Nn + col;
                    float2 rr = *(const float2*)(Res + off);
                    float2 w; w.x = v0 + rr.x; w.y = v1 + rr.y;
                    *(float2*)(outF + off) = w;
                } else {
                    v0 = 0.5f * v0 * (1.f + erff(v0 * 0.70710678118654752f));
                    v1 = 0.5f * v1 * (1.f + erff(v1 * 0.70710678118654752f));
                    size_t off = (size_t)m * Nn + col;
                    __nv_bfloat16 h0, l0, h1, l1;
                    split_bf16(v0, h0, l0);
                    split_bf16(v1, h1, l1);
                    outHi[off] = h0; outHi[off + 1] = h1;
                    outLo[off] = l0; outLo[off + 1] = l1;
                }
            }
        }
    }
}

// ===========================================================================
// Flash-style attention (fp32 FMA).  Output -> bf16 hi/lo in [B,S,D].
// ===========================================================================
#define PAD 68
#define ATTN_SMEM (4 * 64 * PAD * 4)

__global__ __launch_bounds__(256) void attention_kernel(
    const float* __restrict__ Q, const float* __restrict__ K,
    const float* __restrict__ V, __nv_bfloat16* __restrict__ Ohi,
    __nv_bfloat16* __restrict__ Olo) {
    extern __shared__ float sm[];
    float* q_sm = sm;
    float* k_sm = sm + 64 * PAD;
    float* v_sm = sm + 2 * 64 * PAD;
    float* p_sm = sm + 3 * 64 * PAD;

    int t = threadIdx.x;
    int bh = blockIdx.y;
    int q0 = blockIdx.x * 64;
    int b_ = bh / Hdim, h_ = bh % Hdim;
    const float* Qb = Q + ((size_t)bh * Sdim + q0) * HDdim;
    const float* Kb = K + (size_t)bh * Sdim * HDdim;
    const float* Vb = V + (size_t)bh * Sdim * HDdim;
    int tq = t >> 4, tk = t & 15;

    #pragma unroll
    for (int r = 0; r < 4; r++) {
        int f = t + r * 256;
        int row = f >> 4, dc = (f & 15) << 2;
        float4 qv = *(const float4*)(Qb + row * HDdim + dc);
        q_sm[(dc + 0) * PAD + row] = qv.x * 0.125f;
        q_sm[(dc + 1) * PAD + row] = qv.y * 0.125f;
        q_sm[(dc + 2) * PAD + row] = qv.z * 0.125f;
        q_sm[(dc + 3) * PAD + row] = qv.w * 0.125f;
    }

    float o_acc[4][4];
    #pragma unroll
    for (int i = 0; i < 4; i++)
        #pragma unroll
        for (int j = 0; j < 4; j++) o_acc[i][j] = 0.f;
    float m_run[4] = {-1e30f, -1e30f, -1e30f, -1e30f};
    float l_run[4] = {0.f, 0.f, 0.f, 0.f};

    for (int kt = 0; kt < Sdim / 64; kt++) {
        __syncthreads();
        const float* Kt = Kb + (size_t)kt * 64 * HDdim;
        const float* Vt = Vb + (size_t)kt * 64 * HDdim;
        #pragma unroll
        for (int r = 0; r < 4; r++) {
            int f = t + r * 256;
            int row = f >> 4, dc = (f & 15) << 2;
            float4 kv = *(const float4*)(Kt + row * HDdim + dc);
            k_sm[(dc + 0) * PAD + row] = kv.x;
            k_sm[(dc + 1) * PAD + row] = kv.y;
            k_sm[(dc + 2) * PAD + row] = kv.z;
            k_sm[(dc + 3) * PAD + row] = kv.w;
            float4 vv = *(const float4*)(Vt + row * HDdim + dc);
            *(float4*)&v_sm[row * PAD + dc] = vv;
        }
        __syncthreads();

        float s4[4][4];
        #pragma unroll
        for (int i = 0; i < 4; i++)
            #pragma unroll
            for (int j = 0; j < 4; j++) s4[i][j] = 0.f;
        #pragma unroll 8
        for (int d = 0; d < 64; d++) {
            float4 aq = *(float4*)&q_sm[d * PAD + tq * 4];
            float4 bk = *(float4*)&k_sm[d * PAD + tk * 4];
            float av[4] = {aq.x, aq.y, aq.z, aq.w};
            float bv[4] = {bk.x, bk.y, bk.z, bk.w};
            #pragma unroll
            for (int i = 0; i < 4; i++)
                #pragma unroll
                for (int j = 0; j < 4; j++) s4[i][j] += av[i] * bv[j];
        }

        #pragma unroll
        for (int qi = 0; qi < 4; qi++) {
            float tmax = fmaxf(fmaxf(s4[qi][0], s4[qi][1]),
                               fmaxf(s4[qi][2], s4[qi][3]));
            #pragma unroll
            for (int off = 8; off > 0; off >>= 1)
                tmax = fmaxf(tmax, __shfl_xor_sync(0xffffffffu, tmax, off));
            float m_new = fmaxf(m_run[qi], tmax);
            float alpha = __expf(m_run[qi] - m_new);
            m_run[qi] = m_new;
            float psum = 0.f;
            #pragma unroll
            for (int j = 0; j < 4; j++) {
                s4[qi][j] = __expf(s4[qi][j] - m_new);
                psum += s4[qi][j];
            }
            #pragma unroll
            for (int off = 8; off > 0; off >>= 1)
                psum += __shfl_xor_sync(0xffffffffu, psum, off);
            l_run[qi] = l_run[qi] * alpha + psum;
            #pragma unroll
            for (int j = 0; j < 4; j++) o_acc[qi][j] *= alpha;
            #pragma unroll
            for (int j = 0; j < 4; j++)
                p_sm[(tk * 4 + j) * PAD + tq * 4 + qi] = s4[qi][j];
        }
        __syncthreads();

        #pragma unroll 8
        for (int kk = 0; kk < 64; kk++) {
            float4 pp = *(float4*)&p_sm[kk * PAD + tq * 4];
            float4 vv = *(float4*)&v_sm[kk * PAD + tk * 4];
            float pv[4] = {pp.x, pp.y, pp.z, pp.w};
            float vw[4] = {vv.x, vv.y, vv.z, vv.w};
            #pragma unroll
            for (int i = 0; i < 4; i++)
                #pragma unroll
                for (int j = 0; j < 4; j++) o_acc[i][j] += pv[i] * vw[j];
        }
    }

    #pragma unroll
    for (int qi = 0; qi < 4; qi++) {
        float inv = 1.0f / l_run[qi];
        int qrow = q0 + tq * 4 + qi;
        size_t off = ((size_t)b_ * Sdim + qrow) * Ddim + h_ * HDdim + tk * 4;
        #pragma unroll
        for (int j = 0; j < 4; j++) {
            __nv_bfloat16 hi, lo; split_bf16(o_acc[qi][j] * inv, hi, lo);
            Ohi[off + j] = hi; Olo[off + j] = lo;
        }
    }
}

// ===========================================================================
// Launch
// ===========================================================================
extern "C" void kernel_launch(void* const* d_in, const int* in_sizes, int n_in,
                              void* d_out, int out_size) {
    const float* x   = (const float*)d_in[0];
    const float* Wq  = (const float*)d_in[1];
    const float* bq  = (const float*)d_in[2];
    const float* Wk  = (const float*)d_in[3];
    const float* bk  = (const float*)d_in[4];
    const float* Wv  = (const float*)d_in[5];
    const float* bv  = (const float*)d_in[6];
    const float* Wo  = (const float*)d_in[7];
    const float* bo  = (const float*)d_in[8];
    const float* W1  = (const float*)d_in[9];
    const float* b1  = (const float*)d_in[10];
    const float* W2  = (const float*)d_in[11];
    const float* b2  = (const float*)d_in[12];
    const float* g1  = (const float*)d_in[13];
    const float* be1 = (const float*)d_in[14];
    const float* g2  = (const float*)d_in[15];
    const float* be2 = (const float*)d_in[16];
    float* out = (float*)d_out;

    float *qkv, *x1, *b3;
    __nv_bfloat16 *xnh, *xnl, *ath, *atl, *xn2h, *xn2l, *hh, *hl;
    __nv_bfloat16 *wqh, *wql, *woh, *wol, *w1h, *w1l, *w2h, *w2l;
    cudaGetSymbolAddress((void**)&qkv, g_qkv);
    cudaGetSymbolAddress((void**)&x1, g_x1);
    cudaGetSymbolAddress((void**)&b3, g_b3);
    cudaGetSymbolAddress((void**)&xnh, g_xn_hi);
    cudaGetSymbolAddress((void**)&xnl, g_xn_lo);
    cudaGetSymbolAddress((void**)&ath, g_att_hi);
    cudaGetSymbolAddress((void**)&atl, g_att_lo);
    cudaGetSymbolAddress((void**)&xn2h, g_xn2_hi);
    cudaGetSymbolAddress((void**)&xn2l, g_xn2_lo);
    cudaGetSymbolAddress((void**)&hh, g_h_hi);
    cudaGetSymbolAddress((void**)&hl, g_h_lo);
    cudaGetSymbolAddress((void**)&wqh, g_wqkv_hi);
    cudaGetSymbolAddress((void**)&wql, g_wqkv_lo);
    cudaGetSymbolAddress((void**)&woh, g_wo_hi);
    cudaGetSymbolAddress((void**)&wol, g_wo_lo);
    cudaGetSymbolAddress((void**)&w1h, g_w1_hi);
    cudaGetSymbolAddress((void**)&w1l, g_w1_lo);
    cudaGetSymbolAddress((void**)&w2h, g_w2_hi);
    cudaGetSymbolAddress((void**)&w2l, g_w2_lo);

    cudaFuncSetAttribute(gemm_tc<0>, cudaFuncAttributeMaxDynamicSharedMemorySize, GEMM_SMEM);
    cudaFuncSetAttribute(gemm_tc<1>, cudaFuncAttributeMaxDynamicSharedMemorySize, GEMM_SMEM);
    cudaFuncSetAttribute(gemm_tc<2>, cudaFuncAttributeMaxDynamicSharedMemorySize, GEMM_SMEM);
    cudaFuncSetAttribute(attention_kernel, cudaFuncAttributeMaxDynamicSharedMemorySize, ATTN_SMEM);

    dim3 blk(256);
    // weight prep (independent of activations; runs up front)
    wsplit<<<dim3(32, 32), blk>>>(Wq, wqh, wql, Ddim, Ddim);
    wsplit<<<dim3(32, 32), blk>>>(Wk, wqh + DDsz, wql + DDsz, Ddim, Ddim);
    wsplit<<<dim3(32, 32), blk>>>(Wv, wqh + 2 * DDsz, wql + 2 * DDsz, Ddim, Ddim);
    wsplit<<<dim3(32, 32), blk>>>(Wo, woh, wol, Ddim, Ddim);
    wsplit<<<dim3(128, 32), blk>>>(W1, w1h, w1l, Ddim, Fdim);
    wsplit<<<dim3(32, 128), blk>>>(W2, w2h, w2l, Fdim, Ddim);
    bias3<<<12, blk>>>(bq, bk, bv, b3);

    ln_split<<<Mdim, blk>>>(x, g1, be1, xnh, xnl);
    gemm_tc<0><<<dim3(24, 64), blk, GEMM_SMEM>>>(xnh, xnl, wqh, wql, b3,
                                                 nullptr, qkv, nullptr, nullptr, 3072, Ddim);
    attention_kernel<<<dim3(Sdim / 64, Bdim * Hdim), blk, ATTN_SMEM>>>(
        qkv, qkv + MDsz, qkv + 2 * MDsz, ath, atl);
    gemm_tc<1><<<dim3(8, 64), blk, GEMM_SMEM>>>(ath, atl, woh, wol, bo,
                                                x, x1, nullptr, nullptr, Ddim, Ddim);
    ln_split<<<Mdim, blk>>>(x1, g2, be2, xn2h, xn2l);
    gemm_tc<2><<<dim3(32, 64), blk, GEMM_SMEM>>>(xn2h, xn2l, w1h, w1l, b1,
                                                 nullptr, nullptr, hh, hl, Fdim, Ddim);
    gemm_tc<1><<<dim3(8, 64), blk, GEMM_SMEM>>>(hh, hl, w2h, w2l, b2,
                                                x1, out, nullptr, nullptr, Ddim, Fdim);
}

// round 8
// speedup vs baseline: 2.5021x; 1.4842x over previous
#include <cuda_runtime.h>
#include <cuda_bf16.h>
#include <math.h>
#include <stdint.h>

#define Bdim 4
#define Sdim 2048
#define Ddim 1024
#define Hdim 16
#define HDdim 64
#define Fdim 4096
#define Mdim (Bdim * Sdim)   // 8192
#define EPS 1e-5f

#define MDsz ((size_t)Mdim * Ddim)
#define MFsz ((size_t)Mdim * Fdim)
#define DDsz ((size_t)Ddim * Ddim)
#define DFsz ((size_t)Ddim * Fdim)

// ---------------- scratch (static device arrays; allocation-free) ----------
__device__ float g_x1[MDsz];               // residual after attention
__device__ float g_b3[3 * Ddim];           // concat bias q|k|v
// qkv split blob: [qh, ql, kh, kl, vh, vl], each MDsz, layout [B,H,S,HD]
__device__ __nv_bfloat16 g_qkvs[6 * MDsz];
__device__ __nv_bfloat16 g_xn_hi[MDsz],  g_xn_lo[MDsz];
__device__ __nv_bfloat16 g_att_hi[MDsz], g_att_lo[MDsz];
__device__ __nv_bfloat16 g_xn2_hi[MDsz], g_xn2_lo[MDsz];
__device__ __nv_bfloat16 g_h_hi[MFsz],   g_h_lo[MFsz];
__device__ __nv_bfloat16 g_wqkv_hi[3*DDsz], g_wqkv_lo[3*DDsz];  // [3072,1024] K-major
__device__ __nv_bfloat16 g_wo_hi[DDsz],  g_wo_lo[DDsz];
__device__ __nv_bfloat16 g_w1_hi[DFsz],  g_w1_lo[DFsz];
__device__ __nv_bfloat16 g_w2_hi[DFsz],  g_w2_lo[DFsz];

// ---------------- PTX helpers (baseline sm_80+ only) ------------------------
__device__ __forceinline__ uint32_t smem_u32(const void* p) {
    uint32_t a;
    asm("{ .reg .u64 t; cvta.to.shared.u64 t, %1; cvt.u32.u64 %0, t; }"
        : "=r"(a) : "l"(p));
    return a;
}
#define CPA16(d, s) asm volatile("cp.async.cg.shared.global [%0], [%1], 16;" :: "r"(d), "l"(s))
#define CPCOMMIT()  asm volatile("cp.async.commit_group;" ::: "memory")
#define CPWAIT1()   asm volatile("cp.async.wait_group 1;" ::: "memory")
#define CPWAIT0()   asm volatile("cp.async.wait_group 0;" ::: "memory")

#define LDSM4(r0, r1, r2, r3, a) \
    asm volatile("ldmatrix.sync.aligned.m8n8.x4.shared.b16 {%0,%1,%2,%3}, [%4];" \
                 : "=r"(r0), "=r"(r1), "=r"(r2), "=r"(r3) : "r"(a))
#define LDSM4T(r0, r1, r2, r3, a) \
    asm volatile("ldmatrix.sync.aligned.m8n8.x4.trans.shared.b16 {%0,%1,%2,%3}, [%4];" \
                 : "=r"(r0), "=r"(r1), "=r"(r2), "=r"(r3) : "r"(a))
#define LDSM2(r0, r1, a) \
    asm volatile("ldmatrix.sync.aligned.m8n8.x2.shared.b16 {%0,%1}, [%2];" \
                 : "=r"(r0), "=r"(r1) : "r"(a))
#define MMA16816(c, a, b) \
    asm volatile("mma.sync.aligned.m16n8k16.row.col.f32.bf16.bf16.f32 " \
                 "{%0,%1,%2,%3}, {%4,%5,%6,%7}, {%8,%9}, {%0,%1,%2,%3};" \
                 : "+f"((c)[0]), "+f"((c)[1]), "+f"((c)[2]), "+f"((c)[3]) \
                 : "r"((a)[0]), "r"((a)[1]), "r"((a)[2]), "r"((a)[3]), \
                   "r"((b)[0]), "r"((b)[1]))

__device__ __forceinline__ void split_bf16(float v, __nv_bfloat16& hi, __nv_bfloat16& lo) {
    hi = __float2bfloat16(v);
    lo = __float2bfloat16(v - __bfloat162float(hi));
}
__device__ __forceinline__ uint32_t pack2(__nv_bfloat16 a, __nv_bfloat16 b) {
    return (uint32_t)__bfloat16_as_ushort(a) | ((uint32_t)__bfloat16_as_ushort(b) << 16);
}
// hi/lo split of a pair, packed for mma A-fragments
__device__ __forceinline__ void packsplit(float x, float y, uint32_t& hi, uint32_t& lo) {
    __nv_bfloat16 hx, lx, hy, ly;
    split_bf16(x, hx, lx);
    split_bf16(y, hy, ly);
    hi = pack2(hx, hy);
    lo = pack2(lx, ly);
}
// fast exp2 (no MUFU): degree-5 poly + exponent bit add. x <= 0 expected.
__device__ __forceinline__ float fexp2(float x) {
    x = fmaxf(x, -80.f);
    int ni = __float2int_rn(x);
    float r = x - (float)ni;
    float p = 1.33335581e-3f;
    p = fmaf(p, r, 9.61812911e-3f);
    p = fmaf(p, r, 5.55041086e-2f);
    p = fmaf(p, r, 2.40226507e-1f);
    p = fmaf(p, r, 6.93147182e-1f);
    p = fmaf(p, r, 1.0f);
    return __int_as_float(__float_as_int(p) + (ni << 23));
}

// ===========================================================================
// LayerNorm -> bf16 hi/lo split.
// ===========================================================================
__global__ __launch_bounds__(256) void ln_split(const float* __restrict__ X,
                                                const float* __restrict__ G,
                                                const float* __restrict__ Bt,
                                                __nv_bfloat16* __restrict__ Yhi,
                                                __nv_bfloat16* __restrict__ Ylo) {
    int row = blockIdx.x, t = threadIdx.x;
    float4 v = ((const float4*)(X + (size_t)row * Ddim))[t];
    float s  = v.x + v.y + v.z + v.w;
    float ss = v.x*v.x + v.y*v.y + v.z*v.z + v.w*v.w;
    #pragma unroll
    for (int off = 16; off > 0; off >>= 1) {
        s  += __shfl_xor_sync(0xffffffffu, s,  off);
        ss += __shfl_xor_sync(0xffffffffu, ss, off);
    }
    __shared__ float rs[8], rq[8];
    int wid = t >> 5, lane = t & 31;
    if (lane == 0) { rs[wid] = s; rq[wid] = ss; }
    __syncthreads();
    float S_ = 0.f, Q_ = 0.f;
    #pragma unroll
    for (int i = 0; i < 8; i++) { S_ += rs[i]; Q_ += rq[i]; }
    float mu = S_ * (1.0f / Ddim);
    float rstd = rsqrtf(Q_ * (1.0f / Ddim) - mu * mu + EPS);
    float4 g4 = ((const float4*)G)[t];
    float4 b4 = ((const float4*)Bt)[t];
    float y[4] = {(v.x-mu)*rstd*g4.x + b4.x, (v.y-mu)*rstd*g4.y + b4.y,
                  (v.z-mu)*rstd*g4.z + b4.z, (v.w-mu)*rstd*g4.w + b4.w};
    size_t off = (size_t)row * Ddim + t * 4;
    #pragma unroll
    for (int i = 0; i < 4; i++) {
        __nv_bfloat16 hi, lo; split_bf16(y[i], hi, lo);
        Yhi[off + i] = hi; Ylo[off + i] = lo;
    }
}

// ===========================================================================
// Weight transpose + split: W[K,N] fp32 -> Whi/Wlo [N,K] bf16 (K-major).
// ===========================================================================
__global__ __launch_bounds__(256) void wsplit(const float* __restrict__ W,
                                              __nv_bfloat16* __restrict__ Whi,
                                              __nv_bfloat16* __restrict__ Wlo,
                                              int K, int N) {
    __shared__ float tile[32][33];
    int tx = threadIdx.x & 31, ty = threadIdx.x >> 5;
    int bn = blockIdx.x * 32, bk = blockIdx.y * 32;
    #pragma unroll
    for (int i = 0; i < 4; i++)
        tile[ty + i*8][tx] = W[(size_t)(bk + ty + i*8) * N + bn + tx];
    __syncthreads();
    #pragma unroll
    for (int i = 0; i < 4; i++) {
        int n = bn + ty + i*8, k = bk + tx;
        __nv_bfloat16 hi, lo; split_bf16(tile[tx][ty + i*8], hi, lo);
        Whi[(size_t)n * K + k] = hi;
        Wlo[(size_t)n * K + k] = lo;
    }
}

__global__ void bias3(const float* a, const float* b, const float* c, float* o) {
    int i = blockIdx.x * 256 + threadIdx.x;
    if (i < 3072)
        o[i] = i < 1024 ? a[i] : (i < 2048 ? b[i - 1024] : c[i - 2048]);
}

// ===========================================================================
// split-bf16 GEMM on mma.sync.  C[M,N] = A @ B^T, B K-major [N,K].
// BM=BN=128, BK=32, 256 thr = 8 warps (2m x 4n), warp tile 64x32.
// MODE 0: QKV -> bf16 hi/lo split blob [B,H,S,HD] (q scaled by 0.125*log2e)
// MODE 1: +bias +Res -> fp32     MODE 2: gelu(+bias) -> bf16 hi/lo
// ===========================================================================
#define STG_ARR 10240
#define STG_BYTES (4 * STG_ARR)
#define GEMM_SMEM (2 * STG_BYTES)

template <int MODE>
__global__ __launch_bounds__(256) void gemm_tc(
    const __nv_bfloat16* __restrict__ Ahi, const __nv_bfloat16* __restrict__ Alo,
    const __nv_bfloat16* __restrict__ Bhi, const __nv_bfloat16* __restrict__ Blo,
    const float* __restrict__ bias, const float* __restrict__ Res,
    float* __restrict__ outF, __nv_bfloat16* __restrict__ outHi,
    __nv_bfloat16* __restrict__ outLo, int Nn, int Kn) {
    extern __shared__ char smem[];
    uint32_t sb = smem_u32(smem);
    int t = threadIdx.x;
    int lane = t & 31, wid = t >> 5;
    int warp_m = wid >> 2;
    int warp_n = wid & 3;
    int bm = blockIdx.y * 128, bn = blockIdx.x * 128;
    int ktiles = Kn >> 5;

    auto prefetch = [&](int kt, int s) {
        uint32_t stg = sb + s * STG_BYTES;
        #pragma unroll
        for (int it = 0; it < 8; it++) {
            int cid = t + it * 256;
            int arr = cid >> 9;
            int rem = cid & 511;
            int row = rem >> 2, ch = rem & 3;
            uint32_t dst = stg + arr * STG_ARR + row * 80 + ch * 16;
            const __nv_bfloat16* src;
            if (arr == 0)      src = Ahi + (size_t)(bm + row) * Kn;
            else if (arr == 1) src = Alo + (size_t)(bm + row) * Kn;
            else if (arr == 2) src = Bhi + (size_t)(bn + row) * Kn;
            else               src = Blo + (size_t)(bn + row) * Kn;
            src += kt * 32 + ch * 8;
            CPA16(dst, src);
        }
        CPCOMMIT();
    };

    float acc[4][4][4];
    #pragma unroll
    for (int i = 0; i < 4; i++)
        #pragma unroll
        for (int j = 0; j < 4; j++)
            #pragma unroll
            for (int r = 0; r < 4; r++) acc[i][j][r] = 0.f;

    prefetch(0, 0);
    if (ktiles > 1) prefetch(1, 1);

    int aLr = lane & 15, aLc = lane >> 4;
    int bLr = lane & 7,  bLc = (lane >> 3) & 1;

    for (int kt = 0; kt < ktiles; kt++) {
        int s = kt & 1;
        if (kt + 1 < ktiles) { CPWAIT1(); } else { CPWAIT0(); }
        __syncthreads();
        uint32_t stg = sb + s * STG_BYTES;
        uint32_t aHiB = stg,             aLoB = stg + STG_ARR;
        uint32_t bHiB = stg + 2*STG_ARR, bLoB = stg + 3*STG_ARR;

        #pragma unroll
        for (int ks = 0; ks < 2; ks++) {
            int k0 = ks * 16;
            uint32_t ahi[4][4], alo[4][4], bhi[4][2], blo[4][2];
            #pragma unroll
            for (int mt = 0; mt < 4; mt++) {
                uint32_t off = (uint32_t)(warp_m * 64 + mt * 16 + aLr) * 80
                             + (uint32_t)(k0 + aLc * 8) * 2;
                LDSM4(ahi[mt][0], ahi[mt][1], ahi[mt][2], ahi[mt][3], aHiB + off);
                LDSM4(alo[mt][0], alo[mt][1], alo[mt][2], alo[mt][3], aLoB + off);
            }
            #pragma unroll
            for (int nt = 0; nt < 4; nt++) {
                uint32_t off = (uint32_t)(warp_n * 32 + nt * 8 + bLr) * 80
                             + (uint32_t)(k0 + bLc * 8) * 2;
                LDSM2(bhi[nt][0], bhi[nt][1], bHiB + off);
                LDSM2(blo[nt][0], blo[nt][1], bLoB + off);
            }
            #pragma unroll
            for (int mt = 0; mt < 4; mt++)
                #pragma unroll
                for (int nt = 0; nt < 4; nt++) {
                    MMA16816(acc[mt][nt], ahi[mt], bhi[nt]);
                    MMA16816(acc[mt][nt], alo[mt], bhi[nt]);
                    MMA16816(acc[mt][nt], ahi[mt], blo[nt]);
                }
        }
        __syncthreads();
        if (kt + 2 < ktiles) prefetch(kt + 2, s);
    }

    // ---------------- epilogue ----------------
    int g = lane >> 2, t4 = lane & 3;
    int m_base = bm + warp_m * 64;
    int n_base = bn + warp_n * 32;

    float bcol[4][2];
    #pragma unroll
    for (int nt = 0; nt < 4; nt++) {
        int col = n_base + nt * 8 + t4 * 2;
        bcol[nt][0] = bias[col];
        bcol[nt][1] = bias[col + 1];
    }

    #pragma unroll
    for (int mt = 0; mt < 4; mt++) {
        #pragma unroll
        for (int half = 0; half < 2; half++) {
            int m = m_base + mt * 16 + g + half * 8;
            int b_ = m >> 11, s_ = m & 2047;
            #pragma unroll
            for (int nt = 0; nt < 4; nt++) {
                int col = n_base + nt * 8 + t4 * 2;
                float v0 = acc[mt][nt][half * 2 + 0] + bcol[nt][0];
                float v1 = acc[mt][nt][half * 2 + 1] + bcol[nt][1];
                if (MODE == 0) {
                    int mat = col >> 10;                 // 0=q,1=k,2=v
                    int nn = col & 1023;
                    int h_ = nn >> 6, hd = nn & 63;
                    if (mat == 0) {                      // fold 1/8 * log2(e)
                        v0 *= 0.180336878f;
                        v1 *= 0.180336878f;
                    }
                    __nv_bfloat16 h0, l0, h1, l1;
                    split_bf16(v0, h0, l0);
                    split_bf16(v1, h1, l1);
                    __nv_bfloat16* hiA = outHi + (size_t)mat * 2 * MDsz;
                    __nv_bfloat16* loA = hiA + MDsz;
                    size_t off = ((((size_t)b_ * Hdim + h_) * Sdim + s_) << 6) + hd;
                    *(uint32_t*)(hiA + off) = pack2(h0, h1);
                    *(uint32_t*)(loA + off) = pack2(l0, l1);
                } else if (MODE == 1) {
                    size_t off = (size_t)m * Nn + col;
                    float2 rr = *(const float2*)(Res + off);
                    float2 w; w.x = v0 + rr.x; w.y = v1 + rr.y;
                    *(float2*)(outF + off) = w;
                } else {
                    v0 = 0.5f * v0 * (1.f + erff(v0 * 0.70710678118654752f));
                    v1 = 0.5f * v1 * (1.f + erff(v1 * 0.70710678118654752f));
                    size_t off = (size_t)m * Nn + col;
                    __nv_bfloat16 h0, l0, h1, l1;
                    split_bf16(v0, h0, l0);
                    split_bf16(v1, h1, l1);
                    *(uint32_t*)(outHi + off) = pack2(h0, h1);
                    *(uint32_t*)(outLo + off) = pack2(l0, l1);
                }
            }
        }
    }
}

// ===========================================================================
// Tensor-core flash attention (split-bf16, base-2 softmax, FFMA exp2).
// Grid: (S/128, B*H), 256 thr = 8 warps, each warp 16 q-rows.
// K-tiles of 64 keys, double-buffered cp.async.
// smem rows stride 144B (72 bf16): conflict-free ldmatrix.
// ===========================================================================
#define SROW 144
#define AQ_BYTES (128 * SROW)              // 18432 per Q array
#define KV_ARR (64 * SROW)                 // 9216 per K/V array
#define KV_STG (4 * KV_ARR)                // 36864 per stage
#define ATTN_SMEM (2 * AQ_BYTES + 2 * KV_STG)   // 110592

__global__ __launch_bounds__(256) void attn_tc(
    const __nv_bfloat16* __restrict__ qkvs,
    __nv_bfloat16* __restrict__ Ohi, __nv_bfloat16* __restrict__ Olo) {
    extern __shared__ char smem[];
    uint32_t sb = smem_u32(smem);
    int t = threadIdx.x;
    int lane = t & 31, wid = t >> 5;
    int g = lane >> 2, t4 = lane & 3;
    int bh = blockIdx.y;
    int b_ = bh >> 4, h_ = bh & 15;
    int q0 = blockIdx.x * 128;

    const __nv_bfloat16* Qh = qkvs + ((size_t)bh * Sdim + q0) * HDdim;
    const __nv_bfloat16* Ql = Qh + MDsz;
    const __nv_bfloat16* Kh = qkvs + 2 * MDsz + (size_t)bh * Sdim * HDdim;
    const __nv_bfloat16* Kl = Kh + MDsz;
    const __nv_bfloat16* Vh = Kh + 2 * MDsz;
    const __nv_bfloat16* Vl = Kh + 3 * MDsz;

    uint32_t QHs = sb, QLs = sb + AQ_BYTES;
    uint32_t KVs = sb + 2 * AQ_BYTES;

    // load Q tile (128 rows x 64 bf16, hi+lo)
    #pragma unroll
    for (int it = 0; it < 8; it++) {
        int cid = t + it * 256;              // 0..2047
        int arr = cid >> 10;
        int rem = cid & 1023;
        int row = rem >> 3, ch = rem & 7;
        uint32_t dst = (arr ? QLs : QHs) + row * SROW + ch * 16;
        const __nv_bfloat16* src = (arr ? Ql : Qh) + (size_t)row * HDdim + ch * 8;
        CPA16(dst, src);
    }
    CPCOMMIT();

    auto prefetch = [&](int kt, int s) {
        uint32_t stg = KVs + s * KV_STG;
        #pragma unroll
        for (int it = 0; it < 8; it++) {
            int cid = t + it * 256;
            int arr = cid >> 9;              // 0 Kh,1 Kl,2 Vh,3 Vl
            int rem = cid & 511;
            int row = rem >> 3, ch = rem & 7;
            uint32_t dst = stg + arr * KV_ARR + row * SROW + ch * 16;
            const __nv_bfloat16* src;
            if (arr == 0)      src = Kh;
            else if (arr == 1) src = Kl;
            else if (arr == 2) src = Vh;
            else               src = Vl;
            src += (size_t)(kt * 64 + row) * HDdim + ch * 8;
            CPA16(dst, src);
        }
        CPCOMMIT();
    };
    prefetch(0, 0);
    CPWAIT1();               // Q done (kv0 may still be in flight)
    __syncthreads();

    // Q fragments (persistent): 4 k-chunks, hi+lo
    uint32_t qhf[4][4], qlf[4][4];
    {
        int mrow = wid * 16;
        int aLr = lane & 15, aLc = lane >> 4;
        #pragma unroll
        for (int kc = 0; kc < 4; kc++) {
            uint32_t off = (uint32_t)(mrow + aLr) * SROW + (uint32_t)(kc * 16 + aLc * 8) * 2;
            LDSM4(qhf[kc][0], qhf[kc][1], qhf[kc][2], qhf[kc][3], QHs + off);
            LDSM4(qlf[kc][0], qlf[kc][1], qlf[kc][2], qlf[kc][3], QLs + off);
        }
    }

    float o[8][4];
    #pragma unroll
    for (int i = 0; i < 8; i++)
        #pragma unroll
        for (int j = 0; j < 4; j++) o[i][j] = 0.f;
    float m0r = -1e30f, m1r = -1e30f, l0r = 0.f, l1r = 0.f;

    const int KT = Sdim / 64;    // 32
    for (int kt = 0; kt < KT; kt++) {
        int s = kt & 1;
        if (kt + 1 < KT) { prefetch(kt + 1, s ^ 1); CPWAIT1(); }
        else             { CPWAIT0(); }
        __syncthreads();
        uint32_t stg = KVs + s * KV_STG;
        uint32_t KHb = stg, KLb = stg + KV_ARR;
        uint32_t VHb = stg + 2 * KV_ARR, VLb = stg + 3 * KV_ARR;

        // ---- scores: c[nt] = S[16 q x 8 keys], nt over 64 keys ----
        float c[8][4];
        #pragma unroll
        for (int i = 0; i < 8; i++)
            #pragma unroll
            for (int j = 0; j < 4; j++) c[i][j] = 0.f;

        int kRow = (lane & 7);
        int kCol = ((lane >> 3) << 3);   // 0,8,16,24
        #pragma unroll
        for (int nt = 0; nt < 8; nt++) {
            uint32_t base = (uint32_t)(nt * 8 + kRow) * SROW + kCol * 2;
            uint32_t khf[8], klf[8];
            LDSM4(khf[0], khf[1], khf[2], khf[3], KHb + base);
            LDSM4(khf[4], khf[5], khf[6], khf[7], KHb + base + 64);
            LDSM4(klf[0], klf[1], klf[2], klf[3], KLb + base);
            LDSM4(klf[4], klf[5], klf[6], klf[7], KLb + base + 64);
            #pragma unroll
            for (int kc = 0; kc < 4; kc++) {
                MMA16816(c[nt], qhf[kc], &khf[kc * 2]);
                MMA16816(c[nt], qlf[kc], &khf[kc * 2]);
                MMA16816(c[nt], qhf[kc], &klf[kc * 2]);
            }
        }

        // ---- online softmax (base-2 domain) ----
        float m0 = -1e30f, m1 = -1e30f;
        #pragma unroll
        for (int nt = 0; nt < 8; nt++) {
            m0 = fmaxf(m0, fmaxf(c[nt][0], c[nt][1]));
            m1 = fmaxf(m1, fmaxf(c[nt][2], c[nt][3]));
        }
        m0 = fmaxf(m0, __shfl_xor_sync(0xffffffffu, m0, 1));
        m0 = fmaxf(m0, __shfl_xor_sync(0xffffffffu, m0, 2));
        m1 = fmaxf(m1, __shfl_xor_sync(0xffffffffu, m1, 1));
        m1 = fmaxf(m1, __shfl_xor_sync(0xffffffffu, m1, 2));
        float mn0 = fmaxf(m0r, m0), mn1 = fmaxf(m1r, m1);
        float a0 = fexp2(m0r - mn0), a1 = fexp2(m1r - mn1);
        float s0 = 0.f, s1 = 0.f;
        #pragma unroll
        for (int nt = 0; nt < 8; nt++) {
            c[nt][0] = fexp2(c[nt][0] - mn0);
            c[nt][1] = fexp2(c[nt][1] - mn0);
            c[nt][2] = fexp2(c[nt][2] - mn1);
            c[nt][3] = fexp2(c[nt][3] - mn1);
            s0 += c[nt][0] + c[nt][1];
            s1 += c[nt][2] + c[nt][3];
        }
        s0 += __shfl_xor_sync(0xffffffffu, s0, 1);
        s0 += __shfl_xor_sync(0xffffffffu, s0, 2);
        s1 += __shfl_xor_sync(0xffffffffu, s1, 1);
        s1 += __shfl_xor_sync(0xffffffffu, s1, 2);
        l0r = l0r * a0 + s0;
        l1r = l1r * a1 + s1;
        m0r = mn0; m1r = mn1;
        #pragma unroll
        for (int i = 0; i < 8; i++) {
            o[i][0] *= a0; o[i][1] *= a0;
            o[i][2] *= a1; o[i][3] *= a1;
        }

        // ---- P fragments (registers, hi/lo split) ----
        uint32_t ph[4][4], pl[4][4];
        #pragma unroll
        for (int kc = 0; kc < 4; kc++) {
            packsplit(c[2*kc][0],   c[2*kc][1],   ph[kc][0], pl[kc][0]);
            packsplit(c[2*kc][2],   c[2*kc][3],   ph[kc][1], pl[kc][1]);
            packsplit(c[2*kc+1][0], c[2*kc+1][1], ph[kc][2], pl[kc][2]);
            packsplit(c[2*kc+1][2], c[2*kc+1][3], ph[kc][3], pl[kc][3]);
        }

        // ---- O += P @ V  (V via ldmatrix.trans) ----
        int vRow = ((lane >> 3) & 1) * 8 + (lane & 7);   // key within 16
        int vCol = ((lane >> 4) << 3);                   // 0 or 8
        #pragma unroll
        for (int np = 0; np < 4; np++) {
            #pragma unroll
            for (int kc = 0; kc < 4; kc++) {
                uint32_t base = (uint32_t)(kc * 16 + vRow) * SROW
                              + (uint32_t)(np * 16 + vCol) * 2;
                uint32_t vhf[4], vlf[4];
                LDSM4T(vhf[0], vhf[1], vhf[2], vhf[3], VHb + base);
                LDSM4T(vlf[0], vlf[1], vlf[2], vlf[3], VLb + base);
                MMA16816(o[2*np],   ph[kc], &vhf[0]);
                MMA16816(o[2*np],   pl[kc], &vhf[0]);
                MMA16816(o[2*np],   ph[kc], &vlf[0]);
                MMA16816(o[2*np+1], ph[kc], &vhf[2]);
                MMA16816(o[2*np+1], pl[kc], &vhf[2]);
                MMA16816(o[2*np+1], ph[kc], &vlf[2]);
            }
        }
        __syncthreads();
    }

    // ---- epilogue: divide by l, write bf16 hi/lo to [B,S,D] ----
    float inv0 = 1.0f / l0r, inv1 = 1.0f / l1r;
    int r0 = q0 + wid * 16 + g, r1 = r0 + 8;
    size_t base0 = ((size_t)b_ * Sdim + r0) * Ddim + h_ * HDdim;
    size_t base1 = ((size_t)b_ * Sdim + r1) * Ddim + h_ * HDdim;
    #pragma unroll
    for (int nt = 0; nt < 8; nt++) {
        int col = nt * 8 + t4 * 2;
        __nv_bfloat16 h0, l0, h1, l1;
        split_bf16(o[nt][0] * inv0, h0, l0);
        split_bf16(o[nt][1] * inv0, h1, l1);
        *(uint32_t*)(Ohi + base0 + col) = pack2(h0, h1);
        *(uint32_t*)(Olo + base0 + col) = pack2(l0, l1);
        split_bf16(o[nt][2] * inv1, h0, l0);
        split_bf16(o[nt][3] * inv1, h1, l1);
        *(uint32_t*)(Ohi + base1 + col) = pack2(h0, h1);
        *(uint32_t*)(Olo + base1 + col) = pack2(l0, l1);
    }
}

// ===========================================================================
// Launch
// ===========================================================================
extern "C" void kernel_launch(void* const* d_in, const int* in_sizes, int n_in,
                              void* d_out, int out_size) {
    const float* x   = (const float*)d_in[0];
    const float* Wq  = (const float*)d_in[1];
    const float* bq  = (const float*)d_in[2];
    const float* Wk  = (const float*)d_in[3];
    const float* bk  = (const float*)d_in[4];
    const float* Wv  = (const float*)d_in[5];
    const float* bv  = (const float*)d_in[6];
    const float* Wo  = (const float*)d_in[7];
    const float* bo  = (const float*)d_in[8];
    const float* W1  = (const float*)d_in[9];
    const float* b1  = (const float*)d_in[10];
    const float* W2  = (const float*)d_in[11];
    const float* b2  = (const float*)d_in[12];
    const float* g1  = (const float*)d_in[13];
    const float* be1 = (const float*)d_in[14];
    const float* g2  = (const float*)d_in[15];
    const float* be2 = (const float*)d_in[16];
    float* out = (float*)d_out;

    float *x1, *b3;
    __nv_bfloat16 *qkvs, *xnh, *xnl, *ath, *atl, *xn2h, *xn2l, *hh, *hl;
    __nv_bfloat16 *wqh, *wql, *woh, *wol, *w1h, *w1l, *w2h, *w2l;
    cudaGetSymbolAddress((void**)&x1, g_x1);
    cudaGetSymbolAddress((void**)&b3, g_b3);
    cudaGetSymbolAddress((void**)&qkvs, g_qkvs);
    cudaGetSymbolAddress((void**)&xnh, g_xn_hi);
    cudaGetSymbolAddress((void**)&xnl, g_xn_lo);
    cudaGetSymbolAddress((void**)&ath, g_att_hi);
    cudaGetSymbolAddress((void**)&atl, g_att_lo);
    cudaGetSymbolAddress((void**)&xn2h, g_xn2_hi);
    cudaGetSymbolAddress((void**)&xn2l, g_xn2_lo);
    cudaGetSymbolAddress((void**)&hh, g_h_hi);
    cudaGetSymbolAddress((void**)&hl, g_h_lo);
    cudaGetSymbolAddress((void**)&wqh, g_wqkv_hi);
    cudaGetSymbolAddress((void**)&wql, g_wqkv_lo);
    cudaGetSymbolAddress((void**)&woh, g_wo_hi);
    cudaGetSymbolAddress((void**)&wol, g_wo_lo);
    cudaGetSymbolAddress((void**)&w1h, g_w1_hi);
    cudaGetSymbolAddress((void**)&w1l, g_w1_lo);
    cudaGetSymbolAddress((void**)&w2h, g_w2_hi);
    cudaGetSymbolAddress((void**)&w2l, g_w2_lo);

    cudaFuncSetAttribute(gemm_tc<0>, cudaFuncAttributeMaxDynamicSharedMemorySize, GEMM_SMEM);
    cudaFuncSetAttribute(gemm_tc<1>, cudaFuncAttributeMaxDynamicSharedMemorySize, GEMM_SMEM);
    cudaFuncSetAttribute(gemm_tc<2>, cudaFuncAttributeMaxDynamicSharedMemorySize, GEMM_SMEM);
    cudaFuncSetAttribute(attn_tc, cudaFuncAttributeMaxDynamicSharedMemorySize, ATTN_SMEM);

    dim3 blk(256);
    wsplit<<<dim3(32, 32), blk>>>(Wq, wqh, wql, Ddim, Ddim);
    wsplit<<<dim3(32, 32), blk>>>(Wk, wqh + DDsz, wql + DDsz, Ddim, Ddim);
    wsplit<<<dim3(32, 32), blk>>>(Wv, wqh + 2 * DDsz, wql + 2 * DDsz, Ddim, Ddim);
    wsplit<<<dim3(32, 32), blk>>>(Wo, woh, wol, Ddim, Ddim);
    wsplit<<<dim3(128, 32), blk>>>(W1, w1h, w1l, Ddim, Fdim);
    wsplit<<<dim3(32, 128), blk>>>(W2, w2h, w2l, Fdim, Ddim);
    bias3<<<12, blk>>>(bq, bk, bv, b3);

    ln_split<<<Mdim, blk>>>(x, g1, be1, xnh, xnl);
    gemm_tc<0><<<dim3(24, 64), blk, GEMM_SMEM>>>(xnh, xnl, wqh, wql, b3,
                                                 nullptr, nullptr, qkvs, nullptr, 3072, Ddim);
    attn_tc<<<dim3(Sdim / 128, Bdim * Hdim), blk, ATTN_SMEM>>>(qkvs, ath, atl);
    gemm_tc<1><<<dim3(8, 64), blk, GEMM_SMEM>>>(ath, atl, woh, wol, bo,
                                                x, x1, nullptr, nullptr, Ddim, Ddim);
    ln_split<<<Mdim, blk>>>(x1, g2, be2, xn2h, xn2l);
    gemm_tc<2><<<dim3(32, 64), blk, GEMM_SMEM>>>(xn2h, xn2l, w1h, w1l, b1,
                                                 nullptr, nullptr, hh, hl, Fdim, Ddim);
    gemm_tc<1><<<dim3(8, 64), blk, GEMM_SMEM>>>(hh, hl, w2h, w2l, b2,
                                                x1, out, nullptr, nullptr, Ddim, Fdim);
}